// round 12
// baseline (speedup 1.0000x reference)
#include <cuda_runtime.h>
#include <cuda_bf16.h>
#include <math.h>

#define B_  64
#define T_  1024
#define VOCAB_ 10000

typedef unsigned long long ull;

// ---- static scratch (no allocations allowed) ----
__device__ float g_xgf[B_ * T_ * 128];       // 33.5 MB : per-gate prescaled xg
__device__ float g_h [B_ * T_ * 32];         //  8.4 MB : LSTM hidden states
__device__ float g_pacc[B_ * 2 * T_ * 32];   // 16.8 MB : unnormalized ctx partials per s-chunk
__device__ float g_pz [B_ * 2 * T_];         //  0.5 MB : partial softmax sums per s-chunk

#define LOG2E 1.4426950408889634f

// ---- helpers ----
__device__ __forceinline__ float ex2f(float x) {
    float r; asm("ex2.approx.f32 %0, %1;" : "=f"(r) : "f"(x)); return r;
}
__device__ __forceinline__ float rcpf(float x) {
    float r; asm("rcp.approx.f32 %0, %1;" : "=f"(r) : "f"(x)); return r;
}
__device__ __forceinline__ ull pk(float a, float b) {
    ull r; asm("mov.b64 %0, {%1, %2};" : "=l"(r) : "f"(a), "f"(b)); return r;
}
__device__ __forceinline__ void upk(ull v, float& a, float& b) {
    asm("mov.b64 {%0, %1}, %2;" : "=f"(a), "=f"(b) : "l"(v));
}
__device__ __forceinline__ ull ffma2(ull a, ull b, ull c) {
    ull r; asm("fma.rn.f32x2 %0, %1, %2, %3;" : "=l"(r) : "l"(a), "l"(b), "l"(c)); return r;
}
__device__ __forceinline__ ull add2(ull a, ull b) {
    ull r; asm("add.rn.f32x2 %0, %1, %2;" : "=l"(r) : "l"(a), "l"(b)); return r;
}
__device__ __forceinline__ ull mul2(ull a, ull b) {
    ull r; asm("mul.rn.f32x2 %0, %1, %2;" : "=l"(r) : "l"(a), "l"(b)); return r;
}

// ============================================================
// Kernel 1: zero-token index queue (last 100 zeros, ascending, -1 padded front)
// ============================================================
__global__ void queue_kernel(const int* __restrict__ in, float* __restrict__ out,
                             int out_size) {
    if (out_size < 2248) return;
    float* q = out + (out_size - 200);
    int tid = threadIdx.x;                 // 0..1023
    int base = tid * 64;
    ull m = 0;
    const int4* p4 = (const int4*)(in + base);
#pragma unroll
    for (int k = 0; k < 16; k++) {
        int4 v = p4[k];
        if (v.x == 0 || v.x >= VOCAB_) m |= 1ull << (4 * k + 0);
        if (v.y == 0 || v.y >= VOCAB_) m |= 1ull << (4 * k + 1);
        if (v.z == 0 || v.z >= VOCAB_) m |= 1ull << (4 * k + 2);
        if (v.w == 0 || v.w >= VOCAB_) m |= 1ull << (4 * k + 3);
    }
    int cnt = __popcll(m);
    int lane = tid & 31, wid = tid >> 5;
    int v = cnt;
#pragma unroll
    for (int o = 1; o < 32; o <<= 1) {
        int t = __shfl_up_sync(0xffffffffu, v, o);
        if (lane >= o) v += t;
    }
    __shared__ int wsum[32];
    __shared__ int woff[32];
    __shared__ int stot;
    if (lane == 31) wsum[wid] = v;
    __syncthreads();
    if (wid == 0) {
        int x = wsum[lane];
        int y = x;
#pragma unroll
        for (int o = 1; o < 32; o <<= 1) {
            int t = __shfl_up_sync(0xffffffffu, y, o);
            if (lane >= o) y += t;
        }
        woff[lane] = y - x;
        if (lane == 31) stot = y;
    }
    __syncthreads();
    int total = stot;
    int excl = woff[wid] + v - cnt;
    if (tid < 200) q[tid] = -1.0f;
    __syncthreads();
    int r = excl;
    ull mm = m;
    while (mm) {
        int k = __ffsll(mm) - 1;
        mm &= mm - 1;
        int slot = r - total + 100;
        if (slot >= 0) {
            int p = base + k;
            q[slot * 2]     = (float)(p >> 10);
            q[slot * 2 + 1] = (float)(p & 1023);
        }
        r++;
    }
}

// ============================================================
// Kernel 2: xg = b_lstm + emb[id]@k, per-gate floats, PRE-SCALED:
// gates i,f,o by -log2e (sigmoid via ex2), gate g by 2*log2e (tanh via ex2).
// Layout: g_xgf[(b*T+t)*128 + gate*32 + unit]
// ============================================================
__global__ __launch_bounds__(256) void xg_kernel(const int* __restrict__ inp,
                                                 const float* __restrict__ emb,
                                                 const float* __restrict__ klstm,
                                                 const float* __restrict__ blstm) {
    int b  = blockIdx.x >> 3;
    int tb = (blockIdx.x & 7) * 128;
    int tid = threadIdx.x, lane = tid & 31, w = tid >> 5;
    float kr[4][32];
#pragma unroll
    for (int d = 0; d < 32; d++)
#pragma unroll
        for (int qq = 0; qq < 4; qq++) kr[qq][d] = klstm[d * 128 + qq * 32 + lane];
    float br[4];
#pragma unroll
    for (int qq = 0; qq < 4; qq++) br[qq] = blstm[qq * 32 + lane];

    for (int i = 0; i < 16; i++) {
        int t = tb + w * 16 + i;
        int u = inp[b * T_ + t];
        int id = (u < VOCAB_) ? u : 0;
        float ev = emb[id * 32 + lane];
        float a0 = br[0], a1 = br[1], a2 = br[2], a3 = br[3];
#pragma unroll
        for (int d = 0; d < 32; d++) {
            float e = __shfl_sync(0xffffffffu, ev, d);
            a0 = fmaf(e, kr[0][d], a0);
            a1 = fmaf(e, kr[1][d], a1);
            a2 = fmaf(e, kr[2][d], a2);
            a3 = fmaf(e, kr[3][d], a3);
        }
        float* o = g_xgf + (b * T_ + t) * 128;
        o[lane]      = a0 * (-LOG2E);        // i
        o[32 + lane] = a1 * (-LOG2E);        // f
        o[64 + lane] = a2 * (2.0f * LOG2E);  // g
        o[96 + lane] = a3 * (-LOG2E);        // o
    }
}

// ============================================================
// Kernel 3: LSTM recurrence. 64 blocks x 128 threads (one batch per block).
// Warp = gate (lane = unit). ONE __syncthreads per step:
// every warp redundantly computes the packed c/h tail (lane pair = units
// 2j,2j+1) and writes its OWN private hsh copy; acts double-buffered.
// ============================================================
__global__ __launch_bounds__(128, 1) void lstm_kernel(const float* __restrict__ rk) {
    int b = blockIdx.x;
    int tid = threadIdx.x;
    int lane = tid & 31, w = tid >> 5;         // w = gate
    const float FOUR_L = 4.0f * LOG2E, TWO_L = 2.0f * LOG2E;
    float scale = (w == 2) ? TWO_L : (-LOG2E);
    ull rkp[16];
#pragma unroll
    for (int j = 0; j < 16; j++) {
        rkp[j] = pk(rk[(2 * j) * 128 + w * 32 + lane] * scale,
                    rk[(2 * j + 1) * 128 + w * 32 + lane] * scale);
    }
    __shared__ ull hsh[4][16];       // per-warp private packed (h2j, h2j+1)
    __shared__ float acts[2][128];   // double-buffered activations
    if (lane < 16) hsh[w][lane] = pk(0.f, 0.f);
    ull c2 = pk(0.f, 0.f);           // c pair (units 2jc,2jc+1), scaled by 2*log2e
    int jc = lane & 15;
    float* hb = g_h + b * T_ * 32;
    const float* xgb = g_xgf + b * T_ * 128 + w * 32 + lane;
    float xq0 = xgb[0];
    float xq1 = xgb[128];
    float xq2 = xgb[256];
    float xq3 = xgb[384];
    __syncthreads();
    const ull z64 = pk(0.f, 0.f);

#define LSTM_STEP(XQ, TT)                                                     \
    {                                                                         \
        ull za = pk(XQ, 0.f), zb = z64;                                       \
        if ((TT) + 4 < T_) XQ = xgb[((TT) + 4) * 128];                        \
        const ulonglong2* hv = (const ulonglong2*)hsh[w];                     \
        _Pragma("unroll")                                                     \
        for (int j = 0; j < 8; j++) {                                         \
            ulonglong2 vv = hv[j];                                            \
            za = ffma2(vv.x, rkp[2 * j],     za);                             \
            zb = ffma2(vv.y, rkp[2 * j + 1], zb);                             \
        }                                                                     \
        float zl, zh;                                                         \
        upk(add2(za, zb), zl, zh);                                            \
        float z = zl + zh;                                                    \
        float a;                                                              \
        if (w == 2) a = fmaf(-FOUR_L, rcpf(ex2f(z) + 1.f), TWO_L);            \
        else        a = rcpf(1.f + ex2f(z));                                  \
        acts[(TT) & 1][w * 32 + lane] = a;                                    \
        __syncthreads();                                                      \
        const float* ab = acts[(TT) & 1];                                     \
        ull ai2 = *(const ull*)(ab + 2 * jc);                                 \
        ull af2 = *(const ull*)(ab + 32 + 2 * jc);                            \
        ull ag2 = *(const ull*)(ab + 64 + 2 * jc);                            \
        ull ao2 = *(const ull*)(ab + 96 + 2 * jc);                            \
        c2 = ffma2(af2, c2, mul2(ai2, ag2));                                  \
        float cl, ch;                                                         \
        upk(c2, cl, ch);                                                      \
        float tl = fmaf(-2.f, rcpf(ex2f(cl) + 1.f), 1.f);                     \
        float th = fmaf(-2.f, rcpf(ex2f(ch) + 1.f), 1.f);                     \
        ull h2v = mul2(ao2, pk(tl, th));                                      \
        if (lane < 16) {                                                      \
            hsh[w][lane] = h2v;                                               \
            if (w == 0) *(ull*)(hb + (TT) * 32 + 2 * lane) = h2v;             \
        }                                                                     \
        __syncwarp();                                                         \
    }

    for (int t = 0; t < T_; t += 4) {
        LSTM_STEP(xq0, t);
        LSTM_STEP(xq1, t + 1);
        LSTM_STEP(xq2, t + 2);
        LSTM_STEP(xq3, t + 3);
    }
#undef LSTM_STEP
}

// ============================================================
// Kernel 4: attention partials. grid (8, 64): row-tile(4) x chunk(2) x b.
// Block = 128 threads, TWO query rows per thread (r0 = tile*256+tid,
// r1 = r0+128) sharing each key load -> halves crossbar traffic per FMA.
// 2 blocks/SM (reg budget 256 -> no spills).
// ht pre-scaled by log2e -> p = ex2(dot). Partial Z/acc to gmem.
// ============================================================
#define ATTN_SMEM (512 * 32 * 4)
__global__ __launch_bounds__(128, 2) void attn_kernel() {
    extern __shared__ float hs[];
    int tile = blockIdx.x >> 1, cid = blockIdx.x & 1;
    int b = blockIdx.y;
    int tid = threadIdx.x;
    const float* hbase = g_h + b * (T_ * 32);
    {   // stage this chunk's 512 keys (64KB)
        const float4* src = (const float4*)(hbase + cid * 512 * 32);
        float4* dst = (float4*)hs;
        for (int i = tid; i < 4096; i += 128) dst[i] = src[i];
    }
    int r0 = tile * 256 + tid;
    int r1 = r0 + 128;
    ull ht0[16], ht1[16];
    {
        const float4* ha = (const float4*)(hbase + r0 * 32);
        const float4* hc = (const float4*)(hbase + r1 * 32);
#pragma unroll
        for (int j = 0; j < 8; j++) {
            float4 a = ha[j];
            ht0[2 * j]     = pk(a.x * LOG2E, a.y * LOG2E);
            ht0[2 * j + 1] = pk(a.z * LOG2E, a.w * LOG2E);
            float4 c = hc[j];
            ht1[2 * j]     = pk(c.x * LOG2E, c.y * LOG2E);
            ht1[2 * j + 1] = pk(c.z * LOG2E, c.w * LOG2E);
        }
    }
    __syncthreads();
    const ull z64 = pk(0.f, 0.f);
    ull acc0[16], acc1[16];
#pragma unroll
    for (int k = 0; k < 16; k++) { acc0[k] = z64; acc1[k] = z64; }
    float Z0 = 0.f, Z1 = 0.f;

    for (int s = 0; s < 512; s++) {
        const ulonglong2* hv = (const ulonglong2*)(hs + s * 32);  // uniform -> broadcast
        ull hp[16];
#pragma unroll
        for (int j = 0; j < 8; j++) {
            ulonglong2 v = hv[j];
            hp[2 * j] = v.x; hp[2 * j + 1] = v.y;
        }
        ull d1 = ffma2(hp[0], ht0[0], z64);
        ull d2 = ffma2(hp[1], ht0[1], z64);
        ull e1 = ffma2(hp[0], ht1[0], z64);
        ull e2 = ffma2(hp[1], ht1[1], z64);
#pragma unroll
        for (int k = 2; k < 16; k += 2) {
            d1 = ffma2(hp[k],     ht0[k],     d1);
            d2 = ffma2(hp[k + 1], ht0[k + 1], d2);
            e1 = ffma2(hp[k],     ht1[k],     e1);
            e2 = ffma2(hp[k + 1], ht1[k + 1], e2);
        }
        float a, bb, c, dd;
        upk(add2(d1, d2), a, bb);
        upk(add2(e1, e2), c, dd);
        float p0 = ex2f(a + bb);           // dots pre-scaled by log2e
        float p1 = ex2f(c + dd);
        Z0 += p0; Z1 += p1;
        ull pp0 = pk(p0, p0), pp1 = pk(p1, p1);
#pragma unroll
        for (int k = 0; k < 16; k++) {
            acc0[k] = ffma2(pp0, hp[k], acc0[k]);
            acc1[k] = ffma2(pp1, hp[k], acc1[k]);
        }
    }
    int orow0 = (b * 2 + cid) * T_ + r0;
    int orow1 = (b * 2 + cid) * T_ + r1;
    g_pz[orow0] = Z0;
    g_pz[orow1] = Z1;
    float4* po0 = (float4*)(g_pacc + (size_t)orow0 * 32);
    float4* po1 = (float4*)(g_pacc + (size_t)orow1 * 32);
#pragma unroll
    for (int k = 0; k < 8; k++) {
        float x0, y0, x1, y1;
        upk(acc0[2 * k],     x0, y0);
        upk(acc0[2 * k + 1], x1, y1);
        po0[k] = make_float4(x0, y0, x1, y1);
        upk(acc1[2 * k],     x0, y0);
        upk(acc1[2 * k + 1], x1, y1);
        po1[k] = make_float4(x0, y0, x1, y1);
    }
}

// ============================================================
// Kernel 5: combine partials -> ctx -> y = ctx^T h -> MLP -> out. grid 64.
// ============================================================
__global__ __launch_bounds__(256) void combine_final(const float* __restrict__ W1,
                                                     const float* __restrict__ b1,
                                                     const float* __restrict__ W2,
                                                     const float* __restrict__ b2,
                                                     float* __restrict__ out) {
    __shared__ float sctx[128 * 36];   // padded stride 36 (16B-aligned rows)
    __shared__ float sh[128 * 32];
    int b = blockIdx.x, tid = threadIdx.x;
    int dd = tid >> 3, ee = (tid & 7) * 4;
    float4 y4 = make_float4(0.f, 0.f, 0.f, 0.f);
    const float* pz0 = g_pz + (b * 2) * T_;
    const float* pz1 = g_pz + (b * 2 + 1) * T_;

    for (int tb = 0; tb < 8; tb++) {
        {   // stage ctx: 2 threads per t (halves of 16 dims)
            int t = tb * 128 + (tid >> 1);
            int half = (tid & 1) * 16;
            float inv = 1.f / (pz0[t] + pz1[t]);
            const float4* pa0 = (const float4*)(g_pacc + ((size_t)(b * 2) * T_ + t) * 32 + half);
            const float4* pa1 = (const float4*)(g_pacc + ((size_t)(b * 2 + 1) * T_ + t) * 32 + half);
            float4* so = (float4*)(sctx + (tid >> 1) * 36 + half);
#pragma unroll
            for (int q = 0; q < 4; q++) {
                float4 u = pa0[q], v = pa1[q];
                so[q] = make_float4((u.x + v.x) * inv, (u.y + v.y) * inv,
                                    (u.z + v.z) * inv, (u.w + v.w) * inv);
            }
        }
        {   // stage h tile
            const float4* hsrc = (const float4*)(g_h + b * (T_ * 32) + tb * 128 * 32);
            float4* hdst = (float4*)sh;
#pragma unroll
            for (int q = 0; q < 4; q++) hdst[tid + 256 * q] = hsrc[tid + 256 * q];
        }
        __syncthreads();
        for (int t2 = 0; t2 < 128; t2++) {
            float cv = sctx[t2 * 36 + dd];
            float4 hv = *(const float4*)(sh + t2 * 32 + ee);
            y4.x = fmaf(cv, hv.x, y4.x);
            y4.y = fmaf(cv, hv.y, y4.y);
            y4.z = fmaf(cv, hv.z, y4.z);
            y4.w = fmaf(cv, hv.w, y4.w);
        }
        __syncthreads();
    }
    // y -> smem (reuse sctx as flat [32][32])
    float* ysh = sctx;
    *(float4*)(ysh + dd * 32 + ee) = y4;
    __syncthreads();
    if (tid < 32) {
        int d = tid;
        float acc = b2[0];
        for (int e = 0; e < 32; e++) {
            float s = b1[e];
#pragma unroll
            for (int kk = 0; kk < 32; kk++)
                s = fmaf(ysh[d * 32 + kk], W1[kk * 32 + e], s);
            s = fmaxf(s, 0.f);
            acc = fmaf(s, W2[e], acc);
        }
        out[b * 32 + d] = 1.0f / (1.0f + __expf(-acc));
    }
}

// ============================================================
extern "C" void kernel_launch(void* const* d_in, const int* in_sizes, int n_in,
                              void* d_out, int out_size) {
    const int*   inputs = (const int*)  d_in[0];
    const float* emb    = (const float*)d_in[1];
    const float* klstm  = (const float*)d_in[2];
    const float* rklstm = (const float*)d_in[3];
    const float* blstm  = (const float*)d_in[4];
    const float* W1     = (const float*)d_in[5];
    const float* b1     = (const float*)d_in[6];
    const float* W2     = (const float*)d_in[7];
    const float* b2     = (const float*)d_in[8];
    float* out = (float*)d_out;

    cudaFuncSetAttribute(attn_kernel, cudaFuncAttributeMaxDynamicSharedMemorySize,
                         ATTN_SMEM);

    queue_kernel<<<1, 1024>>>(inputs, out, out_size);
    xg_kernel<<<512, 256>>>(inputs, emb, klstm, blstm);
    lstm_kernel<<<64, 128>>>(rklstm);
    attn_kernel<<<dim3(8, 64), 128, ATTN_SMEM>>>();
    combine_final<<<64, 256>>>(W1, b1, W2, b2, out);
}

// round 13
// speedup vs baseline: 1.6105x; 1.6105x over previous
#include <cuda_runtime.h>
#include <cuda_bf16.h>
#include <math.h>

#define B_  64
#define T_  1024
#define VOCAB_ 10000

typedef unsigned long long ull;

// ---- static scratch (no allocations allowed) ----
__device__ float g_xgf[B_ * T_ * 128];       // 33.5 MB : per-gate prescaled xg
__device__ float g_h [B_ * T_ * 32];         //  8.4 MB : LSTM hidden states
__device__ float g_pacc[B_ * 2 * T_ * 32];   // 16.8 MB : unnormalized ctx partials per s-chunk
__device__ float g_pz [B_ * 2 * T_];         //  0.5 MB : partial softmax sums per s-chunk

#define LOG2E 1.4426950408889634f

// ---- helpers ----
__device__ __forceinline__ float ex2f(float x) {
    float r; asm("ex2.approx.f32 %0, %1;" : "=f"(r) : "f"(x)); return r;
}
__device__ __forceinline__ float rcpf(float x) {
    float r; asm("rcp.approx.f32 %0, %1;" : "=f"(r) : "f"(x)); return r;
}
__device__ __forceinline__ ull pk(float a, float b) {
    ull r; asm("mov.b64 %0, {%1, %2};" : "=l"(r) : "f"(a), "f"(b)); return r;
}
__device__ __forceinline__ void upk(ull v, float& a, float& b) {
    asm("mov.b64 {%0, %1}, %2;" : "=f"(a), "=f"(b) : "l"(v));
}
__device__ __forceinline__ ull ffma2(ull a, ull b, ull c) {
    ull r; asm("fma.rn.f32x2 %0, %1, %2, %3;" : "=l"(r) : "l"(a), "l"(b), "l"(c)); return r;
}
__device__ __forceinline__ ull add2(ull a, ull b) {
    ull r; asm("add.rn.f32x2 %0, %1, %2;" : "=l"(r) : "l"(a), "l"(b)); return r;
}

// ============================================================
// Kernel 1: zero-token index queue (last 100 zeros, ascending, -1 padded front)
// ============================================================
__global__ void queue_kernel(const int* __restrict__ in, float* __restrict__ out,
                             int out_size) {
    if (out_size < 2248) return;
    float* q = out + (out_size - 200);
    int tid = threadIdx.x;                 // 0..1023
    int base = tid * 64;
    ull m = 0;
    const int4* p4 = (const int4*)(in + base);
#pragma unroll
    for (int k = 0; k < 16; k++) {
        int4 v = p4[k];
        if (v.x == 0 || v.x >= VOCAB_) m |= 1ull << (4 * k + 0);
        if (v.y == 0 || v.y >= VOCAB_) m |= 1ull << (4 * k + 1);
        if (v.z == 0 || v.z >= VOCAB_) m |= 1ull << (4 * k + 2);
        if (v.w == 0 || v.w >= VOCAB_) m |= 1ull << (4 * k + 3);
    }
    int cnt = __popcll(m);
    int lane = tid & 31, wid = tid >> 5;
    int v = cnt;
#pragma unroll
    for (int o = 1; o < 32; o <<= 1) {
        int t = __shfl_up_sync(0xffffffffu, v, o);
        if (lane >= o) v += t;
    }
    __shared__ int wsum[32];
    __shared__ int woff[32];
    __shared__ int stot;
    if (lane == 31) wsum[wid] = v;
    __syncthreads();
    if (wid == 0) {
        int x = wsum[lane];
        int y = x;
#pragma unroll
        for (int o = 1; o < 32; o <<= 1) {
            int t = __shfl_up_sync(0xffffffffu, y, o);
            if (lane >= o) y += t;
        }
        woff[lane] = y - x;
        if (lane == 31) stot = y;
    }
    __syncthreads();
    int total = stot;
    int excl = woff[wid] + v - cnt;
    if (tid < 200) q[tid] = -1.0f;
    __syncthreads();
    int r = excl;
    ull mm = m;
    while (mm) {
        int k = __ffsll(mm) - 1;
        mm &= mm - 1;
        int slot = r - total + 100;
        if (slot >= 0) {
            int p = base + k;
            q[slot * 2]     = (float)(p >> 10);
            q[slot * 2 + 1] = (float)(p & 1023);
        }
        r++;
    }
}

// ============================================================
// Kernel 2: xg = b_lstm + emb[id]@k, per-gate floats, PRE-SCALED:
// gates i,f,o by -log2e (sigmoid via ex2), gate g by 2*log2e (tanh via ex2).
// Layout: g_xgf[(b*T+t)*128 + gate*32 + unit]
// ============================================================
__global__ __launch_bounds__(256) void xg_kernel(const int* __restrict__ inp,
                                                 const float* __restrict__ emb,
                                                 const float* __restrict__ klstm,
                                                 const float* __restrict__ blstm) {
    int b  = blockIdx.x >> 3;
    int tb = (blockIdx.x & 7) * 128;
    int tid = threadIdx.x, lane = tid & 31, w = tid >> 5;
    float kr[4][32];
#pragma unroll
    for (int d = 0; d < 32; d++)
#pragma unroll
        for (int qq = 0; qq < 4; qq++) kr[qq][d] = klstm[d * 128 + qq * 32 + lane];
    float br[4];
#pragma unroll
    for (int qq = 0; qq < 4; qq++) br[qq] = blstm[qq * 32 + lane];

    for (int i = 0; i < 16; i++) {
        int t = tb + w * 16 + i;
        int u = inp[b * T_ + t];
        int id = (u < VOCAB_) ? u : 0;
        float ev = emb[id * 32 + lane];
        float a0 = br[0], a1 = br[1], a2 = br[2], a3 = br[3];
#pragma unroll
        for (int d = 0; d < 32; d++) {
            float e = __shfl_sync(0xffffffffu, ev, d);
            a0 = fmaf(e, kr[0][d], a0);
            a1 = fmaf(e, kr[1][d], a1);
            a2 = fmaf(e, kr[2][d], a2);
            a3 = fmaf(e, kr[3][d], a3);
        }
        float* o = g_xgf + (b * T_ + t) * 128;
        o[lane]      = a0 * (-LOG2E);        // i
        o[32 + lane] = a1 * (-LOG2E);        // f
        o[64 + lane] = a2 * (2.0f * LOG2E);  // g
        o[96 + lane] = a3 * (-LOG2E);        // o
    }
}

// ============================================================
// Kernel 3: LSTM recurrence. 64 blocks x 128 threads (one batch per block).
// Warp owns 8 units x 4 gates: lane = 4*j + gate, unit u = 8*warp + j.
// Gate acts combined via 4 SHFLs (in-warp); each warp computes c/h for its
// own 8 units. ONE __syncthreads per step (double-buffered hsh).
// ============================================================
__global__ __launch_bounds__(128, 1) void lstm_kernel(const float* __restrict__ rk) {
    int b = blockIdx.x;
    int tid = threadIdx.x;
    int w = tid >> 5, lane = tid & 31;
    int gate = lane & 3, j = lane >> 2;
    int u = 8 * w + j;
    const float FOUR_L = 4.0f * LOG2E, TWO_L = 2.0f * LOG2E;
    float scale = (gate == 2) ? TWO_L : (-LOG2E);
    ull rkp[16];
#pragma unroll
    for (int dd = 0; dd < 16; dd++) {
        rkp[dd] = pk(rk[(2 * dd) * 128 + gate * 32 + u] * scale,
                     rk[(2 * dd + 1) * 128 + gate * 32 + u] * scale);
    }
    __shared__ float hsh[2][32];       // double-buffered h vector
    if (tid < 32) hsh[0][tid] = 0.f;
    float c2 = 0.f;                    // c for unit j, pre-scaled by 2*log2e
    float* hb = g_h + b * T_ * 32;
    const float* xgb = g_xgf + b * T_ * 128 + gate * 32 + u;
    float xq0 = xgb[0];
    float xq1 = xgb[128];
    float xq2 = xgb[256];
    float xq3 = xgb[384];
    __syncthreads();
    const ull z64 = pk(0.f, 0.f);
    int base4 = lane & ~3;

#define LSTM_STEP(XQ, TT)                                                     \
    {                                                                         \
        ull za = pk(XQ, 0.f), zb = z64;                                       \
        if ((TT) + 4 < T_) XQ = xgb[((TT) + 4) * 128];                        \
        const ulonglong2* hv = (const ulonglong2*)hsh[(TT) & 1];              \
        _Pragma("unroll")                                                     \
        for (int q8 = 0; q8 < 8; q8++) {                                      \
            ulonglong2 vv = hv[q8];                                           \
            za = ffma2(vv.x, rkp[2 * q8],     za);                            \
            zb = ffma2(vv.y, rkp[2 * q8 + 1], zb);                            \
        }                                                                     \
        float zl, zh;                                                         \
        upk(add2(za, zb), zl, zh);                                            \
        float z = zl + zh;                                                    \
        float a;                                                              \
        if (gate == 2) a = fmaf(-FOUR_L, rcpf(ex2f(z) + 1.f), TWO_L);         \
        else           a = rcpf(1.f + ex2f(z));                               \
        float ai  = __shfl_sync(0xffffffffu, a, base4);                       \
        float af  = __shfl_sync(0xffffffffu, a, base4 + 1);                   \
        float ag2 = __shfl_sync(0xffffffffu, a, base4 + 2);                   \
        float ao  = __shfl_sync(0xffffffffu, a, base4 + 3);                   \
        c2 = fmaf(af, c2, ai * ag2);                                          \
        float h = ao * fmaf(-2.f, rcpf(ex2f(c2) + 1.f), 1.f);                 \
        if (gate == 0) {                                                      \
            hsh[((TT) & 1) ^ 1][u] = h;                                       \
            hb[(TT) * 32 + u] = h;                                            \
        }                                                                     \
        __syncthreads();                                                      \
    }

    for (int t = 0; t < T_; t += 4) {
        LSTM_STEP(xq0, t);
        LSTM_STEP(xq1, t + 1);
        LSTM_STEP(xq2, t + 2);
        LSTM_STEP(xq3, t + 3);
    }
#undef LSTM_STEP
}

// ============================================================
// Kernel 4: attention partials (R11 config — best measured).
// grid (16, 64): row-tile(8) x chunk(2) x b. 128 threads, 1 row/thread,
// 3 blocks/SM. ht pre-scaled by log2e -> p = ex2(dot). Partials to gmem.
// ============================================================
#define ATTN_SMEM (512 * 32 * 4)
__global__ __launch_bounds__(128, 3) void attn_kernel() {
    extern __shared__ float hs[];
    int tile = blockIdx.x >> 1, cid = blockIdx.x & 1;
    int b = blockIdx.y;
    int tid = threadIdx.x;
    const float* hbase = g_h + b * (T_ * 32);
    {   // stage this chunk's 512 keys (64KB)
        const float4* src = (const float4*)(hbase + cid * 512 * 32);
        float4* dst = (float4*)hs;
        for (int i = tid; i < 4096; i += 128) dst[i] = src[i];
    }
    int r = tile * 128 + tid;
    ull ht[16];
    {
        const float4* hr = (const float4*)(hbase + r * 32);
#pragma unroll
        for (int j = 0; j < 8; j++) {
            float4 a = hr[j];
            ht[2 * j]     = pk(a.x * LOG2E, a.y * LOG2E);
            ht[2 * j + 1] = pk(a.z * LOG2E, a.w * LOG2E);
        }
    }
    __syncthreads();
    const ull z64 = pk(0.f, 0.f);
    ull acc[16];
#pragma unroll
    for (int k = 0; k < 16; k++) acc[k] = z64;
    float Z = 0.f;

    for (int s = 0; s < 512; s++) {
        const ulonglong2* hv = (const ulonglong2*)(hs + s * 32);  // uniform -> broadcast
        ull hp[16];
#pragma unroll
        for (int j = 0; j < 8; j++) {
            ulonglong2 v = hv[j];
            hp[2 * j] = v.x; hp[2 * j + 1] = v.y;
        }
        ull d1 = ffma2(hp[0], ht[0], z64);
        ull d2 = ffma2(hp[1], ht[1], z64);
#pragma unroll
        for (int k = 2; k < 16; k += 2) {
            d1 = ffma2(hp[k],     ht[k],     d1);
            d2 = ffma2(hp[k + 1], ht[k + 1], d2);
        }
        float a, bb;
        upk(add2(d1, d2), a, bb);
        float p = ex2f(a + bb);            // dot pre-scaled by log2e
        Z += p;
        ull pp = pk(p, p);
#pragma unroll
        for (int k = 0; k < 16; k++) acc[k] = ffma2(pp, hp[k], acc[k]);
    }
    int orow = (b * 2 + cid) * T_ + r;
    g_pz[orow] = Z;
    float4* po = (float4*)(g_pacc + (size_t)orow * 32);
#pragma unroll
    for (int k = 0; k < 8; k++) {
        float x0, y0, x1, y1;
        upk(acc[2 * k],     x0, y0);
        upk(acc[2 * k + 1], x1, y1);
        po[k] = make_float4(x0, y0, x1, y1);
    }
}

// ============================================================
// Kernel 5: combine partials -> ctx -> y = ctx^T h -> MLP -> out. grid 64.
// ============================================================
__global__ __launch_bounds__(256) void combine_final(const float* __restrict__ W1,
                                                     const float* __restrict__ b1,
                                                     const float* __restrict__ W2,
                                                     const float* __restrict__ b2,
                                                     float* __restrict__ out) {
    __shared__ float sctx[128 * 36];   // padded stride 36 (16B-aligned rows)
    __shared__ float sh[128 * 32];
    int b = blockIdx.x, tid = threadIdx.x;
    int dd = tid >> 3, ee = (tid & 7) * 4;
    float4 y4 = make_float4(0.f, 0.f, 0.f, 0.f);
    const float* pz0 = g_pz + (b * 2) * T_;
    const float* pz1 = g_pz + (b * 2 + 1) * T_;

    for (int tb = 0; tb < 8; tb++) {
        {   // stage ctx: 2 threads per t (halves of 16 dims)
            int t = tb * 128 + (tid >> 1);
            int half = (tid & 1) * 16;
            float inv = 1.f / (pz0[t] + pz1[t]);
            const float4* pa0 = (const float4*)(g_pacc + ((size_t)(b * 2) * T_ + t) * 32 + half);
            const float4* pa1 = (const float4*)(g_pacc + ((size_t)(b * 2 + 1) * T_ + t) * 32 + half);
            float4* so = (float4*)(sctx + (tid >> 1) * 36 + half);
#pragma unroll
            for (int q = 0; q < 4; q++) {
                float4 u = pa0[q], v = pa1[q];
                so[q] = make_float4((u.x + v.x) * inv, (u.y + v.y) * inv,
                                    (u.z + v.z) * inv, (u.w + v.w) * inv);
            }
        }
        {   // stage h tile
            const float4* hsrc = (const float4*)(g_h + b * (T_ * 32) + tb * 128 * 32);
            float4* hdst = (float4*)sh;
#pragma unroll
            for (int q = 0; q < 4; q++) hdst[tid + 256 * q] = hsrc[tid + 256 * q];
        }
        __syncthreads();
        for (int t2 = 0; t2 < 128; t2++) {
            float cv = sctx[t2 * 36 + dd];
            float4 hv = *(const float4*)(sh + t2 * 32 + ee);
            y4.x = fmaf(cv, hv.x, y4.x);
            y4.y = fmaf(cv, hv.y, y4.y);
            y4.z = fmaf(cv, hv.z, y4.z);
            y4.w = fmaf(cv, hv.w, y4.w);
        }
        __syncthreads();
    }
    // y -> smem (reuse sctx as flat [32][32])
    float* ysh = sctx;
    *(float4*)(ysh + dd * 32 + ee) = y4;
    __syncthreads();
    if (tid < 32) {
        int d = tid;
        float acc = b2[0];
        for (int e = 0; e < 32; e++) {
            float s = b1[e];
#pragma unroll
            for (int kk = 0; kk < 32; kk++)
                s = fmaf(ysh[d * 32 + kk], W1[kk * 32 + e], s);
            s = fmaxf(s, 0.f);
            acc = fmaf(s, W2[e], acc);
        }
        out[b * 32 + d] = 1.0f / (1.0f + __expf(-acc));
    }
}

// ============================================================
extern "C" void kernel_launch(void* const* d_in, const int* in_sizes, int n_in,
                              void* d_out, int out_size) {
    const int*   inputs = (const int*)  d_in[0];
    const float* emb    = (const float*)d_in[1];
    const float* klstm  = (const float*)d_in[2];
    const float* rklstm = (const float*)d_in[3];
    const float* blstm  = (const float*)d_in[4];
    const float* W1     = (const float*)d_in[5];
    const float* b1     = (const float*)d_in[6];
    const float* W2     = (const float*)d_in[7];
    const float* b2     = (const float*)d_in[8];
    float* out = (float*)d_out;

    cudaFuncSetAttribute(attn_kernel, cudaFuncAttributeMaxDynamicSharedMemorySize,
                         ATTN_SMEM);

    queue_kernel<<<1, 1024>>>(inputs, out, out_size);
    xg_kernel<<<512, 256>>>(inputs, emb, klstm, blstm);
    lstm_kernel<<<64, 128>>>(rklstm);
    attn_kernel<<<dim3(16, 64), 128, ATTN_SMEM>>>();
    combine_final<<<64, 256>>>(W1, b1, W2, b2, out);
}